// round 1
// baseline (speedup 1.0000x reference)
#include <cuda_runtime.h>

// GCN 2-layer forward for fixed problem shape.
#define N_NODES 100000
#define N_EDGES 3200000
#define F_IN    512
#define HID     16

// ---------------- device scratch (no allocations allowed) ----------------
__device__ int   g_is64;
__device__ int   g_deg [N_NODES];
__device__ float g_dinv[N_NODES];
__device__ float g_p   [N_NODES * HID];   // pre-scaled features (layer1 then layer2)
__device__ float g_agg [N_NODES * HID];   // aggregation buffer (reused)

// ---------------- dtype detection --------------------------------------
// If edge_index is int64 (little-endian, values in [0,100000)), every odd
// 32-bit word of the buffer is 0. With int32 data those words are random
// node ids (>=1 with overwhelming probability over 256 samples).
__global__ void k_detect(const int* __restrict__ e) {
    if (blockIdx.x == 0 && threadIdx.x == 0) {
        int is64 = 1;
        for (int i = 1; i < 512; i += 2) {
            if (e[i] != 0) { is64 = 0; break; }
        }
        g_is64 = is64;
    }
}

__device__ __forceinline__ int edge_word(const int* __restrict__ e, int idx, int is64) {
    // idx in [0, 2*N_EDGES): logical flat index into int32 edge array
    return is64 ? e[2 * idx] : e[idx];
}

// ---------------- degree / normalization --------------------------------
__global__ void k_init_deg() {
    int i = blockIdx.x * blockDim.x + threadIdx.x;
    if (i < N_NODES) g_deg[i] = 1;   // self-loop pre-counted
}

__global__ void k_deg(const int* __restrict__ e) {
    int i = blockIdx.x * blockDim.x + threadIdx.x;
    if (i >= N_EDGES) return;
    int is64 = g_is64;
    int c = edge_word(e, N_EDGES + i, is64);
    atomicAdd(&g_deg[c], 1);
}

__global__ void k_dinv() {
    int i = blockIdx.x * blockDim.x + threadIdx.x;
    if (i < N_NODES) g_dinv[i] = rsqrtf((float)g_deg[i]);
}

// ---------------- GEMM1: p = (x @ W1) * dinv[row] ------------------------
// 4 rows per thread, W1 broadcast from shared memory (uniform address ->
// conflict-free broadcast LDS), x via coalesced-per-thread float4 streams.
__global__ __launch_bounds__(128) void k_gemm1(const float* __restrict__ x,
                                               const float* __restrict__ W1) {
    __shared__ float sW[F_IN * HID];   // 32 KB
    for (int i = threadIdx.x; i < (F_IN * HID) / 4; i += blockDim.x)
        ((float4*)sW)[i] = ((const float4*)W1)[i];
    __syncthreads();

    int t = blockIdx.x * blockDim.x + threadIdx.x;
    size_t r0 = (size_t)t * 4;
    if (r0 >= N_NODES) return;   // N_NODES % 4 == 0 -> full 4 rows otherwise

    float acc[4][16];
#pragma unroll
    for (int m = 0; m < 4; m++)
#pragma unroll
        for (int j = 0; j < 16; j++) acc[m][j] = 0.f;

    const float* xb = x + r0 * F_IN;

    for (int k = 0; k < F_IN; k += 4) {
        float4 xv[4];
#pragma unroll
        for (int m = 0; m < 4; m++)
            xv[m] = __ldg((const float4*)(xb + (size_t)m * F_IN + k));
#pragma unroll
        for (int kk = 0; kk < 4; kk++) {
            const float4* wp = (const float4*)(sW + (k + kk) * 16);
            float4 w0 = wp[0], w1 = wp[1], w2 = wp[2], w3 = wp[3];
#pragma unroll
            for (int m = 0; m < 4; m++) {
                float xs = (kk == 0) ? xv[m].x : (kk == 1) ? xv[m].y
                          : (kk == 2) ? xv[m].z : xv[m].w;
                acc[m][0]  += xs * w0.x; acc[m][1]  += xs * w0.y;
                acc[m][2]  += xs * w0.z; acc[m][3]  += xs * w0.w;
                acc[m][4]  += xs * w1.x; acc[m][5]  += xs * w1.y;
                acc[m][6]  += xs * w1.z; acc[m][7]  += xs * w1.w;
                acc[m][8]  += xs * w2.x; acc[m][9]  += xs * w2.y;
                acc[m][10] += xs * w2.z; acc[m][11] += xs * w2.w;
                acc[m][12] += xs * w3.x; acc[m][13] += xs * w3.y;
                acc[m][14] += xs * w3.z; acc[m][15] += xs * w3.w;
            }
        }
    }

#pragma unroll
    for (int m = 0; m < 4; m++) {
        float d = g_dinv[r0 + m];
        float4* dst = (float4*)(g_p + (r0 + m) * HID);
#pragma unroll
        for (int q = 0; q < 4; q++) {
            float4 v;
            v.x = acc[m][q * 4 + 0] * d;
            v.y = acc[m][q * 4 + 1] * d;
            v.z = acc[m][q * 4 + 2] * d;
            v.w = acc[m][q * 4 + 3] * d;
            dst[q] = v;
        }
    }
}

// ---------------- zero agg buffer ----------------------------------------
__global__ void k_zero_agg() {
    int i = blockIdx.x * blockDim.x + threadIdx.x;
    if (i < (N_NODES * HID) / 4)
        ((float4*)g_agg)[i] = make_float4(0.f, 0.f, 0.f, 0.f);
}

// ---------------- edge scatter: agg[col] += p[row] * dinv[col] -----------
__global__ void k_scatter(const int* __restrict__ e) {
    int i = blockIdx.x * blockDim.x + threadIdx.x;
    if (i >= N_EDGES) return;
    int is64 = g_is64;
    int r = edge_word(e, i, is64);
    int c = edge_word(e, N_EDGES + i, is64);
    float s = __ldg(&g_dinv[c]);
    const float4* pv = (const float4*)(g_p + (size_t)r * HID);
    float* dst = g_agg + (size_t)c * HID;
#pragma unroll
    for (int q = 0; q < 4; q++) {
        float4 v = __ldg(pv + q);
        asm volatile(
            "red.global.add.v4.f32 [%0], {%1, %2, %3, %4};"
            :: "l"(dst + q * 4),
               "f"(v.x * s), "f"(v.y * s), "f"(v.z * s), "f"(v.w * s)
            : "memory");
    }
}

// ---------------- layer-1 epilogue + layer-2 linear ----------------------
// t = relu(agg1 + selfloop + b1);  p2 = (t @ W2) * dinv   (overwrites g_p)
__global__ void k_layer2(const float* __restrict__ b1,
                         const float* __restrict__ W2) {
    __shared__ float sW2[HID * 16];
    if (threadIdx.x < 64)
        ((float4*)sW2)[threadIdx.x] = ((const float4*)W2)[threadIdx.x];
    __syncthreads();

    int i = blockIdx.x * blockDim.x + threadIdx.x;
    if (i >= N_NODES) return;
    float d = g_dinv[i];

    float t[16];
    const float4* av = (const float4*)(g_agg + (size_t)i * HID);
    const float4* pv = (const float4*)(g_p + (size_t)i * HID);
#pragma unroll
    for (int q = 0; q < 4; q++) {
        float4 a = av[q];
        float4 p = pv[q];
        float4 b = __ldg((const float4*)b1 + q);
        t[q * 4 + 0] = fmaxf(a.x + p.x * d + b.x, 0.f);
        t[q * 4 + 1] = fmaxf(a.y + p.y * d + b.y, 0.f);
        t[q * 4 + 2] = fmaxf(a.z + p.z * d + b.z, 0.f);
        t[q * 4 + 3] = fmaxf(a.w + p.w * d + b.w, 0.f);
    }

    float o[16];
#pragma unroll
    for (int c = 0; c < 16; c++) o[c] = 0.f;
#pragma unroll
    for (int j = 0; j < 16; j++) {
        const float4* wr = (const float4*)(sW2 + j * 16);
        float4 w0 = wr[0], w1 = wr[1], w2 = wr[2], w3 = wr[3];
        float tj = t[j];
        o[0]  += tj * w0.x; o[1]  += tj * w0.y; o[2]  += tj * w0.z; o[3]  += tj * w0.w;
        o[4]  += tj * w1.x; o[5]  += tj * w1.y; o[6]  += tj * w1.z; o[7]  += tj * w1.w;
        o[8]  += tj * w2.x; o[9]  += tj * w2.y; o[10] += tj * w2.z; o[11] += tj * w2.w;
        o[12] += tj * w3.x; o[13] += tj * w3.y; o[14] += tj * w3.z; o[15] += tj * w3.w;
    }

    float4* dst = (float4*)(g_p + (size_t)i * HID);
#pragma unroll
    for (int q = 0; q < 4; q++) {
        float4 v;
        v.x = o[q * 4 + 0] * d; v.y = o[q * 4 + 1] * d;
        v.z = o[q * 4 + 2] * d; v.w = o[q * 4 + 3] * d;
        dst[q] = v;
    }
}

// ---------------- final: +selfloop +b2, log_softmax ----------------------
__global__ void k_final(const float* __restrict__ b2, float* __restrict__ out) {
    int i = blockIdx.x * blockDim.x + threadIdx.x;
    if (i >= N_NODES) return;
    float d = g_dinv[i];

    float o[16];
    const float4* av = (const float4*)(g_agg + (size_t)i * HID);
    const float4* pv = (const float4*)(g_p + (size_t)i * HID);
#pragma unroll
    for (int q = 0; q < 4; q++) {
        float4 a = av[q];
        float4 p = pv[q];
        float4 b = __ldg((const float4*)b2 + q);
        o[q * 4 + 0] = a.x + p.x * d + b.x;
        o[q * 4 + 1] = a.y + p.y * d + b.y;
        o[q * 4 + 2] = a.z + p.z * d + b.z;
        o[q * 4 + 3] = a.w + p.w * d + b.w;
    }

    float m = o[0];
#pragma unroll
    for (int c = 1; c < 16; c++) m = fmaxf(m, o[c]);
    float s = 0.f;
#pragma unroll
    for (int c = 0; c < 16; c++) s += expf(o[c] - m);
    float lse = m + logf(s);

    float4* dst = (float4*)(out + (size_t)i * HID);
#pragma unroll
    for (int q = 0; q < 4; q++) {
        float4 v;
        v.x = o[q * 4 + 0] - lse; v.y = o[q * 4 + 1] - lse;
        v.z = o[q * 4 + 2] - lse; v.w = o[q * 4 + 3] - lse;
        dst[q] = v;
    }
}

// ---------------- host orchestration -------------------------------------
extern "C" void kernel_launch(void* const* d_in, const int* in_sizes, int n_in,
                              void* d_out, int out_size) {
    const float* x  = (const float*)d_in[0];
    const int*   ei = (const int*)d_in[1];
    const float* W1 = (const float*)d_in[2];
    const float* b1 = (const float*)d_in[3];
    const float* W2 = (const float*)d_in[4];
    const float* b2 = (const float*)d_in[5];
    float* out = (float*)d_out;

    const int TB = 256;
    int grid_nodes = (N_NODES + TB - 1) / TB;
    int grid_edges = (N_EDGES + TB - 1) / TB;
    int grid_zero  = ((N_NODES * HID) / 4 + TB - 1) / TB;
    int grid_gemm  = ((N_NODES / 4) + 127) / 128;

    k_detect  <<<1, 1>>>(ei);
    k_init_deg<<<grid_nodes, TB>>>();
    k_deg     <<<grid_edges, TB>>>(ei);
    k_dinv    <<<grid_nodes, TB>>>();
    k_gemm1   <<<grid_gemm, 128>>>(x, W1);

    k_zero_agg<<<grid_zero, TB>>>();
    k_scatter <<<grid_edges, TB>>>(ei);
    k_layer2  <<<grid_nodes, TB>>>(b1, W2);

    k_zero_agg<<<grid_zero, TB>>>();
    k_scatter <<<grid_edges, TB>>>(ei);
    k_final   <<<grid_nodes, TB>>>(b2, out);
}

// round 2
// speedup vs baseline: 1.2483x; 1.2483x over previous
#include <cuda_runtime.h>

// GCN 2-layer forward, fixed shape. CSR-sorted aggregation + f32x2 GEMM.
#define N_NODES 100000
#define N_EDGES 3200000
#define F_IN    512
#define HID     16
#define NB      391            // ceil(N_NODES/256)

// ---------------- device scratch (no allocations allowed) ----------------
__device__ int   g_is64;
__device__ int   g_deg   [NB * 256];      // edge-target histogram (no self-loop)
__device__ int   g_bsum  [NB];
__device__ int   g_boff  [NB];
__device__ int   g_off   [N_NODES + 1];   // CSR offsets
__device__ int   g_cursor[N_NODES];
__device__ int   g_csr   [N_EDGES];       // row ids sorted by col
__device__ float g_dinv  [N_NODES];
__device__ float g_p     [N_NODES * HID]; // pre-scaled features
__device__ float g_agg   [N_NODES * HID];

// ---------------- dtype detection ---------------------------------------
__global__ void k_detect(const int* __restrict__ e) {
    int is64 = 1;
    for (int i = 1; i < 512; i += 2)
        if (e[i] != 0) { is64 = 0; break; }
    g_is64 = is64;
}

__device__ __forceinline__ int edge_word(const int* __restrict__ e, long long idx, int is64) {
    return is64 ? e[2 * idx] : e[idx];
}

// ---------------- histogram ----------------------------------------------
__global__ void k_zero_deg() {
    int i = blockIdx.x * blockDim.x + threadIdx.x;
    g_deg[i] = 0;   // full NB*256 range, padded entries stay 0
}

__global__ void k_hist(const int* __restrict__ e) {
    int i = blockIdx.x * blockDim.x + threadIdx.x;
    if (i >= N_EDGES) return;
    int c = edge_word(e, (long long)N_EDGES + i, g_is64);
    atomicAdd(&g_deg[c], 1);
}

// ---------------- scan (3 tiny kernels) ----------------------------------
__global__ void k_partial() {
    __shared__ int s[256];
    int i = blockIdx.x * 256 + threadIdx.x;
    s[threadIdx.x] = g_deg[i];
    __syncthreads();
    for (int d = 128; d > 0; d >>= 1) {
        if (threadIdx.x < d) s[threadIdx.x] += s[threadIdx.x + d];
        __syncthreads();
    }
    if (threadIdx.x == 0) g_bsum[blockIdx.x] = s[0];
}

__global__ void k_scanb() {
    // single thread: 391 sequential adds, trivial
    int acc = 0;
    for (int b = 0; b < NB; b++) { g_boff[b] = acc; acc += g_bsum[b]; }
    g_off[N_NODES] = acc;   // == N_EDGES
}

__global__ void k_off() {
    __shared__ int s[256];
    int i = blockIdx.x * 256 + threadIdx.x;
    int v = g_deg[i];
    s[threadIdx.x] = v;
    __syncthreads();
    for (int d = 1; d < 256; d <<= 1) {
        int t = (threadIdx.x >= d) ? s[threadIdx.x - d] : 0;
        __syncthreads();
        s[threadIdx.x] += t;
        __syncthreads();
    }
    int excl = s[threadIdx.x] - v + g_boff[blockIdx.x];
    if (i < N_NODES) { g_off[i] = excl; g_cursor[i] = excl; }
}

__global__ void k_dinv() {
    int i = blockIdx.x * blockDim.x + threadIdx.x;
    if (i < N_NODES) g_dinv[i] = rsqrtf((float)(g_deg[i] + 1));  // +1 self-loop
}

// ---------------- CSR bucket fill ----------------------------------------
__global__ void k_build(const int* __restrict__ e) {
    int i = blockIdx.x * blockDim.x + threadIdx.x;
    if (i >= N_EDGES) return;
    int is64 = g_is64;
    int r = edge_word(e, i, is64);
    int c = edge_word(e, (long long)N_EDGES + i, is64);
    int pos = atomicAdd(&g_cursor[c], 1);
    g_csr[pos] = r;
}

// ---------------- GEMM1: p = (x @ W1) * dinv[row], f32x2 FMA -------------
__device__ __forceinline__ void ffma2(unsigned long long& acc,
                                      unsigned long long a,
                                      unsigned long long b) {
    asm("fma.rn.f32x2 %0, %1, %2, %0;" : "+l"(acc) : "l"(a), "l"(b));
}

__device__ __forceinline__ unsigned long long bcast2(float x) {
    unsigned long long r;
    asm("mov.b64 %0, {%1, %1};" : "=l"(r) : "f"(x));
    return r;
}

__global__ __launch_bounds__(256) void k_gemm1(const float* __restrict__ x,
                                               const float* __restrict__ W1) {
    __shared__ float sW[F_IN * HID];   // 32 KB
    for (int i = threadIdx.x; i < (F_IN * HID) / 4; i += blockDim.x)
        ((float4*)sW)[i] = ((const float4*)W1)[i];
    __syncthreads();

    int t = blockIdx.x * blockDim.x + threadIdx.x;
    size_t r0 = (size_t)t * 2;          // 2 rows per thread
    if (r0 >= N_NODES) return;

    unsigned long long acc[2][8];
#pragma unroll
    for (int m = 0; m < 2; m++)
#pragma unroll
        for (int j = 0; j < 8; j++) acc[m][j] = 0ull;

    const float* xb = x + r0 * F_IN;

    for (int k = 0; k < F_IN; k += 4) {
        float4 xv0 = __ldg((const float4*)(xb + k));
        float4 xv1 = __ldg((const float4*)(xb + F_IN + k));
#pragma unroll
        for (int kk = 0; kk < 4; kk++) {
            const unsigned long long* wp =
                (const unsigned long long*)(sW + (k + kk) * 16);
            unsigned long long w0 = wp[0], w1 = wp[1], w2 = wp[2], w3 = wp[3];
            unsigned long long w4 = wp[4], w5 = wp[5], w6 = wp[6], w7 = wp[7];
            float xs0 = (kk == 0) ? xv0.x : (kk == 1) ? xv0.y : (kk == 2) ? xv0.z : xv0.w;
            float xs1 = (kk == 0) ? xv1.x : (kk == 1) ? xv1.y : (kk == 2) ? xv1.z : xv1.w;
            unsigned long long xp0 = bcast2(xs0);
            unsigned long long xp1 = bcast2(xs1);
            ffma2(acc[0][0], xp0, w0); ffma2(acc[0][1], xp0, w1);
            ffma2(acc[0][2], xp0, w2); ffma2(acc[0][3], xp0, w3);
            ffma2(acc[0][4], xp0, w4); ffma2(acc[0][5], xp0, w5);
            ffma2(acc[0][6], xp0, w6); ffma2(acc[0][7], xp0, w7);
            ffma2(acc[1][0], xp1, w0); ffma2(acc[1][1], xp1, w1);
            ffma2(acc[1][2], xp1, w2); ffma2(acc[1][3], xp1, w3);
            ffma2(acc[1][4], xp1, w4); ffma2(acc[1][5], xp1, w5);
            ffma2(acc[1][6], xp1, w6); ffma2(acc[1][7], xp1, w7);
        }
    }

#pragma unroll
    for (int m = 0; m < 2; m++) {
        if (r0 + m >= N_NODES) break;
        float d = g_dinv[r0 + m];
        float* dst = g_p + (r0 + m) * HID;
#pragma unroll
        for (int j = 0; j < 8; j++) {
            float lo, hi;
            asm("mov.b64 {%0, %1}, %2;" : "=f"(lo), "=f"(hi) : "l"(acc[m][j]));
            dst[2 * j]     = lo * d;
            dst[2 * j + 1] = hi * d;
        }
    }
}

// ---------------- aggregation: agg[c] = dinv[c] * sum_{r in CSR[c]} p[r] --
// 4 threads per node, each owns one float4 column-quad.
__global__ __launch_bounds__(256) void k_agg() {
    int t = blockIdx.x * blockDim.x + threadIdx.x;
    int node = t >> 2;
    int q    = t & 3;
    if (node >= N_NODES) return;

    int e   = g_off[node];
    int end = g_off[node + 1];
    float4 a0 = make_float4(0.f, 0.f, 0.f, 0.f);
    float4 a1 = make_float4(0.f, 0.f, 0.f, 0.f);

    // 2-way unrolled for MLP
    for (; e + 2 <= end; e += 2) {
        int r0 = __ldg(&g_csr[e]);
        int r1 = __ldg(&g_csr[e + 1]);
        float4 v0 = __ldg((const float4*)(g_p + (size_t)r0 * HID + q * 4));
        float4 v1 = __ldg((const float4*)(g_p + (size_t)r1 * HID + q * 4));
        a0.x += v0.x; a0.y += v0.y; a0.z += v0.z; a0.w += v0.w;
        a1.x += v1.x; a1.y += v1.y; a1.z += v1.z; a1.w += v1.w;
    }
    if (e < end) {
        int r0 = __ldg(&g_csr[e]);
        float4 v0 = __ldg((const float4*)(g_p + (size_t)r0 * HID + q * 4));
        a0.x += v0.x; a0.y += v0.y; a0.z += v0.z; a0.w += v0.w;
    }

    float d = g_dinv[node];
    float4 r;
    r.x = (a0.x + a1.x) * d; r.y = (a0.y + a1.y) * d;
    r.z = (a0.z + a1.z) * d; r.w = (a0.w + a1.w) * d;
    ((float4*)(g_agg + (size_t)node * HID))[q] = r;
}

// ---------------- layer-1 epilogue + layer-2 linear ----------------------
__global__ void k_layer2(const float* __restrict__ b1,
                         const float* __restrict__ W2) {
    __shared__ float sW2[HID * 16];
    if (threadIdx.x < 64)
        ((float4*)sW2)[threadIdx.x] = ((const float4*)W2)[threadIdx.x];
    __syncthreads();

    int i = blockIdx.x * blockDim.x + threadIdx.x;
    if (i >= N_NODES) return;
    float d = g_dinv[i];

    float t[16];
    const float4* av = (const float4*)(g_agg + (size_t)i * HID);
    const float4* pv = (const float4*)(g_p + (size_t)i * HID);
#pragma unroll
    for (int q = 0; q < 4; q++) {
        float4 a = av[q];
        float4 p = pv[q];
        float4 b = __ldg((const float4*)b1 + q);
        t[q * 4 + 0] = fmaxf(a.x + p.x * d + b.x, 0.f);
        t[q * 4 + 1] = fmaxf(a.y + p.y * d + b.y, 0.f);
        t[q * 4 + 2] = fmaxf(a.z + p.z * d + b.z, 0.f);
        t[q * 4 + 3] = fmaxf(a.w + p.w * d + b.w, 0.f);
    }

    float o[16];
#pragma unroll
    for (int c = 0; c < 16; c++) o[c] = 0.f;
#pragma unroll
    for (int j = 0; j < 16; j++) {
        const float4* wr = (const float4*)(sW2 + j * 16);
        float4 w0 = wr[0], w1 = wr[1], w2 = wr[2], w3 = wr[3];
        float tj = t[j];
        o[0]  += tj * w0.x; o[1]  += tj * w0.y; o[2]  += tj * w0.z; o[3]  += tj * w0.w;
        o[4]  += tj * w1.x; o[5]  += tj * w1.y; o[6]  += tj * w1.z; o[7]  += tj * w1.w;
        o[8]  += tj * w2.x; o[9]  += tj * w2.y; o[10] += tj * w2.z; o[11] += tj * w2.w;
        o[12] += tj * w3.x; o[13] += tj * w3.y; o[14] += tj * w3.z; o[15] += tj * w3.w;
    }

    float4* dst = (float4*)(g_p + (size_t)i * HID);
#pragma unroll
    for (int q = 0; q < 4; q++) {
        float4 v;
        v.x = o[q * 4 + 0] * d; v.y = o[q * 4 + 1] * d;
        v.z = o[q * 4 + 2] * d; v.w = o[q * 4 + 3] * d;
        dst[q] = v;
    }
}

// ---------------- final: +selfloop +b2, log_softmax ----------------------
__global__ void k_final(const float* __restrict__ b2, float* __restrict__ out) {
    int i = blockIdx.x * blockDim.x + threadIdx.x;
    if (i >= N_NODES) return;
    float d = g_dinv[i];

    float o[16];
    const float4* av = (const float4*)(g_agg + (size_t)i * HID);
    const float4* pv = (const float4*)(g_p + (size_t)i * HID);
#pragma unroll
    for (int q = 0; q < 4; q++) {
        float4 a = av[q];
        float4 p = pv[q];
        float4 b = __ldg((const float4*)b2 + q);
        o[q * 4 + 0] = a.x + p.x * d + b.x;
        o[q * 4 + 1] = a.y + p.y * d + b.y;
        o[q * 4 + 2] = a.z + p.z * d + b.z;
        o[q * 4 + 3] = a.w + p.w * d + b.w;
    }

    float m = o[0];
#pragma unroll
    for (int c = 1; c < 16; c++) m = fmaxf(m, o[c]);
    float s = 0.f;
#pragma unroll
    for (int c = 0; c < 16; c++) s += expf(o[c] - m);
    float lse = m + logf(s);

    float4* dst = (float4*)(out + (size_t)i * HID);
#pragma unroll
    for (int q = 0; q < 4; q++) {
        float4 v;
        v.x = o[q * 4 + 0] - lse; v.y = o[q * 4 + 1] - lse;
        v.z = o[q * 4 + 2] - lse; v.w = o[q * 4 + 3] - lse;
        dst[q] = v;
    }
}

// ---------------- host orchestration -------------------------------------
extern "C" void kernel_launch(void* const* d_in, const int* in_sizes, int n_in,
                              void* d_out, int out_size) {
    const float* x  = (const float*)d_in[0];
    const int*   ei = (const int*)d_in[1];
    const float* W1 = (const float*)d_in[2];
    const float* b1 = (const float*)d_in[3];
    const float* W2 = (const float*)d_in[4];
    const float* b2 = (const float*)d_in[5];
    float* out = (float*)d_out;

    const int TB = 256;
    int grid_edges = (N_EDGES + TB - 1) / TB;
    int grid_gemm  = ((N_NODES + 1) / 2 + TB - 1) / TB;
    int grid_agg   = (N_NODES * 4 + TB - 1) / TB;

    k_detect  <<<1, 1>>>(ei);
    k_zero_deg<<<NB, TB>>>();
    k_hist    <<<grid_edges, TB>>>(ei);
    k_partial <<<NB, TB>>>();
    k_scanb   <<<1, 1>>>();
    k_off     <<<NB, TB>>>();
    k_dinv    <<<NB, TB>>>();
    k_build   <<<grid_edges, TB>>>(ei);
    k_gemm1   <<<grid_gemm, TB>>>(x, W1);

    k_agg     <<<grid_agg, TB>>>();
    k_layer2  <<<NB, TB>>>(b1, W2);

    k_agg     <<<grid_agg, TB>>>();
    k_final   <<<NB, TB>>>(b2, out);
}

// round 3
// speedup vs baseline: 1.5430x; 1.2361x over previous
#include <cuda_runtime.h>

// GCN 2-layer forward, fixed shape. CSR aggregation + f32x2 GEMM + 2-stream overlap.
#define N_NODES 100000
#define N_EDGES 3200000
#define F_IN    512
#define HID     16
#define NB      391            // ceil(N_NODES/256)

// ---------------- device scratch (no allocations allowed) ----------------
__device__ int   g_is64;
__device__ int   g_deg   [NB * 256];      // edge-target histogram (no self-loop)
__device__ int   g_bsum  [NB];
__device__ int   g_boff  [NB];
__device__ int   g_off   [N_NODES + 1];   // CSR offsets
__device__ int   g_cursor[N_NODES];
__device__ int   g_csr   [N_EDGES];       // row ids sorted by col
__device__ float g_dinv  [N_NODES];
__device__ float g_p     [N_NODES * HID]; // features (unscaled, then scaled)
__device__ float g_agg   [N_NODES * HID];

// ---------------- dtype detection (parallel) ------------------------------
__global__ void k_detect(const int* __restrict__ e) {
    __shared__ int any;
    if (threadIdx.x == 0) any = 0;
    __syncthreads();
    // int64 little-endian values < 2^31 -> odd words all zero
    if (e[2 * threadIdx.x + 1] != 0) any = 1;
    __syncthreads();
    if (threadIdx.x == 0) g_is64 = !any;
}

// ---------------- histogram ----------------------------------------------
__global__ void k_zero_deg() {
    int i = blockIdx.x * blockDim.x + threadIdx.x;
    g_deg[i] = 0;
}

__global__ void k_hist(const int* __restrict__ e) {
    int i = blockIdx.x * blockDim.x + threadIdx.x;
    if (i >= N_EDGES) return;
    int c;
    if (g_is64) c = (int)((const long long*)e)[(long long)N_EDGES + i];
    else        c = e[N_EDGES + i];
    atomicAdd(&g_deg[c], 1);
}

// ---------------- scan ----------------------------------------------------
__global__ void k_partial() {
    __shared__ int s[256];
    int i = blockIdx.x * 256 + threadIdx.x;
    s[threadIdx.x] = g_deg[i];
    __syncthreads();
    for (int d = 128; d > 0; d >>= 1) {
        if (threadIdx.x < d) s[threadIdx.x] += s[threadIdx.x + d];
        __syncthreads();
    }
    if (threadIdx.x == 0) g_bsum[blockIdx.x] = s[0];
}

__global__ __launch_bounds__(512) void k_scanb() {
    // single-block exclusive scan over NB (<=512) block sums
    __shared__ int s[512];
    int t = threadIdx.x;
    int v = (t < NB) ? g_bsum[t] : 0;
    s[t] = v;
    __syncthreads();
    for (int d = 1; d < 512; d <<= 1) {
        int u = (t >= d) ? s[t - d] : 0;
        __syncthreads();
        s[t] += u;
        __syncthreads();
    }
    if (t < NB) g_boff[t] = s[t] - v;          // exclusive
    if (t == 0) g_off[N_NODES] = s[511];       // == N_EDGES (pad sums are 0)
}

__global__ void k_off() {
    __shared__ int s[256];
    int i = blockIdx.x * 256 + threadIdx.x;
    int v = g_deg[i];
    s[threadIdx.x] = v;
    __syncthreads();
    for (int d = 1; d < 256; d <<= 1) {
        int t = (threadIdx.x >= d) ? s[threadIdx.x - d] : 0;
        __syncthreads();
        s[threadIdx.x] += t;
        __syncthreads();
    }
    int excl = s[threadIdx.x] - v + g_boff[blockIdx.x];
    if (i < N_NODES) { g_off[i] = excl; g_cursor[i] = excl; }
}

__global__ void k_dinv() {
    int i = blockIdx.x * blockDim.x + threadIdx.x;
    if (i < N_NODES) g_dinv[i] = rsqrtf((float)(g_deg[i] + 1));  // +1 self-loop
}

// ---------------- CSR bucket fill ----------------------------------------
__global__ void k_build(const int* __restrict__ e) {
    int i = blockIdx.x * blockDim.x + threadIdx.x;
    if (i >= N_EDGES) return;
    int r, c;
    if (g_is64) {
        r = (int)((const long long*)e)[i];
        c = (int)((const long long*)e)[(long long)N_EDGES + i];
    } else {
        r = e[i];
        c = e[N_EDGES + i];
    }
    int pos = atomicAdd(&g_cursor[c], 1);
    g_csr[pos] = r;
}

// ---------------- GEMM1: p = x @ W1 (unscaled), f32x2 FMA ----------------
__device__ __forceinline__ void ffma2(unsigned long long& acc,
                                      unsigned long long a,
                                      unsigned long long b) {
    asm("fma.rn.f32x2 %0, %1, %2, %0;" : "+l"(acc) : "l"(a), "l"(b));
}

__device__ __forceinline__ unsigned long long bcast2(float x) {
    unsigned long long r;
    asm("mov.b64 %0, {%1, %1};" : "=l"(r) : "f"(x));
    return r;
}

__global__ __launch_bounds__(256) void k_gemm1(const float* __restrict__ x,
                                               const float* __restrict__ W1) {
    __shared__ float sW[F_IN * HID];   // 32 KB
    for (int i = threadIdx.x; i < (F_IN * HID) / 4; i += blockDim.x)
        ((float4*)sW)[i] = ((const float4*)W1)[i];
    __syncthreads();

    int t = blockIdx.x * blockDim.x + threadIdx.x;
    size_t r0 = (size_t)t * 2;          // 2 rows per thread
    if (r0 >= N_NODES) return;

    unsigned long long acc[2][8];
#pragma unroll
    for (int m = 0; m < 2; m++)
#pragma unroll
        for (int j = 0; j < 8; j++) acc[m][j] = 0ull;

    const float* xb = x + r0 * F_IN;

    for (int k = 0; k < F_IN; k += 4) {
        float4 xv0 = __ldg((const float4*)(xb + k));
        float4 xv1 = __ldg((const float4*)(xb + F_IN + k));
#pragma unroll
        for (int kk = 0; kk < 4; kk++) {
            const unsigned long long* wp =
                (const unsigned long long*)(sW + (k + kk) * 16);
            unsigned long long w0 = wp[0], w1 = wp[1], w2 = wp[2], w3 = wp[3];
            unsigned long long w4 = wp[4], w5 = wp[5], w6 = wp[6], w7 = wp[7];
            float xs0 = (kk == 0) ? xv0.x : (kk == 1) ? xv0.y : (kk == 2) ? xv0.z : xv0.w;
            float xs1 = (kk == 0) ? xv1.x : (kk == 1) ? xv1.y : (kk == 2) ? xv1.z : xv1.w;
            unsigned long long xp0 = bcast2(xs0);
            unsigned long long xp1 = bcast2(xs1);
            ffma2(acc[0][0], xp0, w0); ffma2(acc[0][1], xp0, w1);
            ffma2(acc[0][2], xp0, w2); ffma2(acc[0][3], xp0, w3);
            ffma2(acc[0][4], xp0, w4); ffma2(acc[0][5], xp0, w5);
            ffma2(acc[0][6], xp0, w6); ffma2(acc[0][7], xp0, w7);
            ffma2(acc[1][0], xp1, w0); ffma2(acc[1][1], xp1, w1);
            ffma2(acc[1][2], xp1, w2); ffma2(acc[1][3], xp1, w3);
            ffma2(acc[1][4], xp1, w4); ffma2(acc[1][5], xp1, w5);
            ffma2(acc[1][6], xp1, w6); ffma2(acc[1][7], xp1, w7);
        }
    }

#pragma unroll
    for (int m = 0; m < 2; m++) {
        if (r0 + m >= N_NODES) break;
        float* dst = g_p + (r0 + m) * HID;
#pragma unroll
        for (int j = 0; j < 8; j++) {
            float lo, hi;
            asm("mov.b64 {%0, %1}, %2;" : "=f"(lo), "=f"(hi) : "l"(acc[m][j]));
            dst[2 * j]     = lo;
            dst[2 * j + 1] = hi;
        }
    }
}

// ---------------- scale: p[i] *= dinv[i] (after fork-join) ----------------
__global__ void k_scale() {
    int t = blockIdx.x * blockDim.x + threadIdx.x;   // one float4 per thread
    if (t >= N_NODES * 4) return;
    int node = t >> 2;
    float d = g_dinv[node];
    float4 v = ((float4*)g_p)[t];
    v.x *= d; v.y *= d; v.z *= d; v.w *= d;
    ((float4*)g_p)[t] = v;
}

// ---------------- aggregation: agg[c] = dinv[c] * sum_{r in CSR[c]} p[r] --
__global__ __launch_bounds__(256) void k_agg() {
    int t = blockIdx.x * blockDim.x + threadIdx.x;
    int node = t >> 2;
    int q    = t & 3;
    if (node >= N_NODES) return;

    int e   = g_off[node];
    int end = g_off[node + 1];
    float4 a0 = make_float4(0.f, 0.f, 0.f, 0.f);
    float4 a1 = make_float4(0.f, 0.f, 0.f, 0.f);

    for (; e + 2 <= end; e += 2) {
        int r0 = __ldg(&g_csr[e]);
        int r1 = __ldg(&g_csr[e + 1]);
        float4 v0 = __ldg((const float4*)(g_p + (size_t)r0 * HID + q * 4));
        float4 v1 = __ldg((const float4*)(g_p + (size_t)r1 * HID + q * 4));
        a0.x += v0.x; a0.y += v0.y; a0.z += v0.z; a0.w += v0.w;
        a1.x += v1.x; a1.y += v1.y; a1.z += v1.z; a1.w += v1.w;
    }
    if (e < end) {
        int r0 = __ldg(&g_csr[e]);
        float4 v0 = __ldg((const float4*)(g_p + (size_t)r0 * HID + q * 4));
        a0.x += v0.x; a0.y += v0.y; a0.z += v0.z; a0.w += v0.w;
    }

    float d = g_dinv[node];
    float4 r;
    r.x = (a0.x + a1.x) * d; r.y = (a0.y + a1.y) * d;
    r.z = (a0.z + a1.z) * d; r.w = (a0.w + a1.w) * d;
    ((float4*)(g_agg + (size_t)node * HID))[q] = r;
}

// ---------------- layer-1 epilogue + layer-2 linear ----------------------
__global__ void k_layer2(const float* __restrict__ b1,
                         const float* __restrict__ W2) {
    __shared__ float sW2[HID * 16];
    if (threadIdx.x < 64)
        ((float4*)sW2)[threadIdx.x] = ((const float4*)W2)[threadIdx.x];
    __syncthreads();

    int i = blockIdx.x * blockDim.x + threadIdx.x;
    if (i >= N_NODES) return;
    float d = g_dinv[i];

    float t[16];
    const float4* av = (const float4*)(g_agg + (size_t)i * HID);
    const float4* pv = (const float4*)(g_p + (size_t)i * HID);
#pragma unroll
    for (int q = 0; q < 4; q++) {
        float4 a = av[q];
        float4 p = pv[q];
        float4 b = __ldg((const float4*)b1 + q);
        t[q * 4 + 0] = fmaxf(a.x + p.x * d + b.x, 0.f);
        t[q * 4 + 1] = fmaxf(a.y + p.y * d + b.y, 0.f);
        t[q * 4 + 2] = fmaxf(a.z + p.z * d + b.z, 0.f);
        t[q * 4 + 3] = fmaxf(a.w + p.w * d + b.w, 0.f);
    }

    float o[16];
#pragma unroll
    for (int c = 0; c < 16; c++) o[c] = 0.f;
#pragma unroll
    for (int j = 0; j < 16; j++) {
        const float4* wr = (const float4*)(sW2 + j * 16);
        float4 w0 = wr[0], w1 = wr[1], w2 = wr[2], w3 = wr[3];
        float tj = t[j];
        o[0]  += tj * w0.x; o[1]  += tj * w0.y; o[2]  += tj * w0.z; o[3]  += tj * w0.w;
        o[4]  += tj * w1.x; o[5]  += tj * w1.y; o[6]  += tj * w1.z; o[7]  += tj * w1.w;
        o[8]  += tj * w2.x; o[9]  += tj * w2.y; o[10] += tj * w2.z; o[11] += tj * w2.w;
        o[12] += tj * w3.x; o[13] += tj * w3.y; o[14] += tj * w3.z; o[15] += tj * w3.w;
    }

    float4* dst = (float4*)(g_p + (size_t)i * HID);
#pragma unroll
    for (int q = 0; q < 4; q++) {
        float4 v;
        v.x = o[q * 4 + 0] * d; v.y = o[q * 4 + 1] * d;
        v.z = o[q * 4 + 2] * d; v.w = o[q * 4 + 3] * d;
        dst[q] = v;
    }
}

// ---------------- final: +selfloop +b2, log_softmax ----------------------
__global__ void k_final(const float* __restrict__ b2, float* __restrict__ out) {
    int i = blockIdx.x * blockDim.x + threadIdx.x;
    if (i >= N_NODES) return;
    float d = g_dinv[i];

    float o[16];
    const float4* av = (const float4*)(g_agg + (size_t)i * HID);
    const float4* pv = (const float4*)(g_p + (size_t)i * HID);
#pragma unroll
    for (int q = 0; q < 4; q++) {
        float4 a = av[q];
        float4 p = pv[q];
        float4 b = __ldg((const float4*)b2 + q);
        o[q * 4 + 0] = a.x + p.x * d + b.x;
        o[q * 4 + 1] = a.y + p.y * d + b.y;
        o[q * 4 + 2] = a.z + p.z * d + b.z;
        o[q * 4 + 3] = a.w + p.w * d + b.w;
    }

    float m = o[0];
#pragma unroll
    for (int c = 1; c < 16; c++) m = fmaxf(m, o[c]);
    float s = 0.f;
#pragma unroll
    for (int c = 0; c < 16; c++) s += expf(o[c] - m);
    float lse = m + logf(s);

    float4* dst = (float4*)(out + (size_t)i * HID);
#pragma unroll
    for (int q = 0; q < 4; q++) {
        float4 v;
        v.x = o[q * 4 + 0] - lse; v.y = o[q * 4 + 1] - lse;
        v.z = o[q * 4 + 2] - lse; v.w = o[q * 4 + 3] - lse;
        dst[q] = v;
    }
}

// ---------------- host orchestration -------------------------------------
// Fork/join: GEMM1 (features) runs on a side stream concurrently with the
// whole edge-processing chain (hist/scan/build) on the main stream. Host
// code only runs at capture time; the fork/join becomes graph parallelism.
extern "C" void kernel_launch(void* const* d_in, const int* in_sizes, int n_in,
                              void* d_out, int out_size) {
    const float* x  = (const float*)d_in[0];
    const int*   ei = (const int*)d_in[1];
    const float* W1 = (const float*)d_in[2];
    const float* b1 = (const float*)d_in[3];
    const float* W2 = (const float*)d_in[4];
    const float* b2 = (const float*)d_in[5];
    float* out = (float*)d_out;

    const int TB = 256;
    int grid_edges = (N_EDGES + TB - 1) / TB;
    int grid_gemm  = ((N_NODES + 1) / 2 + TB - 1) / TB;
    int grid_agg   = (N_NODES * 4 + TB - 1) / TB;

    cudaStream_t s2;
    cudaEvent_t evFork, evJoin;
    cudaStreamCreateWithFlags(&s2, cudaStreamNonBlocking);
    cudaEventCreateWithFlags(&evFork, cudaEventDisableTiming);
    cudaEventCreateWithFlags(&evJoin, cudaEventDisableTiming);

    // fork: side stream starts immediately
    cudaEventRecord(evFork, 0);
    cudaStreamWaitEvent(s2, evFork, 0);
    k_gemm1<<<grid_gemm, TB, 0, s2>>>(x, W1);
    cudaEventRecord(evJoin, s2);

    // main stream: edge pipeline
    k_detect  <<<1, 256>>>(ei);
    k_zero_deg<<<NB, TB>>>();
    k_hist    <<<grid_edges, TB>>>(ei);
    k_partial <<<NB, TB>>>();
    k_scanb   <<<1, 512>>>();
    k_off     <<<NB, TB>>>();
    k_dinv    <<<NB, TB>>>();
    k_build   <<<grid_edges, TB>>>(ei);

    // join: need both gemm1 (p) and dinv before scaling
    cudaStreamWaitEvent(0, evJoin, 0);
    k_scale   <<<(N_NODES * 4 + TB - 1) / TB, TB>>>();

    k_agg     <<<grid_agg, TB>>>();
    k_layer2  <<<NB, TB>>>(b1, W2);

    k_agg     <<<grid_agg, TB>>>();
    k_final   <<<NB, TB>>>(b2, out);

    // graph retains the dependency structure; stream/event objects are
    // translated into nodes at capture, safe to destroy here.
    cudaStreamDestroy(s2);
    cudaEventDestroy(evFork);
    cudaEventDestroy(evJoin);
}